// round 4
// baseline (speedup 1.0000x reference)
#include <cuda_runtime.h>

#define Nn   2048      // B*S
#define Bv   16
#define Sv   128
#define Hv   256
#define DINv 256
#define DEv  192
#define DRv  64
#define Ev   2032      // B*(S-1)
#define Lv   12
#define NCTA 128       // 16 trees x 8 column groups (= 16 clusters of 8)
#define NTHR 512
#define SMEM_BYTES 196608   // 48K floats: 32K weights + 16K scratch

// packed fp32x2 FMA (sm_103a FFMA2)
#define FFMA2(acc, a, b) asm("fma.rn.f32x2 %0, %1, %2, %0;" : "+l"(acc) : "l"(a), "l"(b))

__device__ __forceinline__ float pairsum(unsigned long long v) {
    float lo, hi;
    asm("mov.b64 {%0, %1}, %2;" : "=f"(lo), "=f"(hi) : "l"(v));
    return lo + hi;
}

// cluster-wide barrier (8 CTAs = one tree); includes L1 invalidate
__device__ __forceinline__ void cluster_bar() {
    asm volatile("barrier.cluster.arrive.aligned;" ::: "memory");
    asm volatile("barrier.cluster.wait.aligned;" ::: "memory");
}

// ---------------- device scratch (no allocations allowed) ----------------
__device__ float g_proj[4][Nn * Hv];   // ix(+b_ix+b_ih), fx(+b_fx+b_fh), ox, ux
__device__ float g_h[Nn * Hv];
__device__ float g_c[Nn * Hv];
__device__ float g_fh[Nn * Hv];        // W_fh . h_n, per node
__device__ float g_pooled[Bv * Hv];
__device__ int   g_coff[Nn + 1];
__device__ int   g_children[Ev];
__device__ int   g_tl_off[512];        // [16][32] per-tree level offsets
__device__ int   g_tl_nodes[Nn];       // per-tree level-bucketed node ids
__device__ int   g_tmax[Bv];

__device__ __forceinline__ float sigf(float x) {
    return 1.0f / (1.0f + __expf(-x));
}

// ---------------- setup: CSR of children + per-tree level buckets ---------
__global__ void setup_kernel(const int* __restrict__ child_idx,
                             const int* __restrict__ parent_idx,
                             const int* __restrict__ node_height) {
    __shared__ int cnt[Nn];
    __shared__ int psm[Ev];
    __shared__ int hsm[Nn];
    __shared__ int part[256];
    __shared__ int lvl[512];
    __shared__ int lfill[512];
    __shared__ int loff[512];
    const int tid = threadIdx.x;               // 1024 threads
    for (int i = tid; i < Nn; i += 1024) { cnt[i] = 0; hsm[i] = node_height[i]; }
    for (int i = tid; i < Ev; i += 1024) psm[i] = parent_idx[i];
    for (int i = tid; i < 512; i += 1024) { lvl[i] = 0; lfill[i] = 0; }
    __syncthreads();
    for (int e = tid; e < Ev; e += 1024) atomicAdd(&cnt[psm[e]], 1);
    for (int n = tid; n < Nn; n += 1024) atomicAdd(&lvl[(n >> 7) * 32 + hsm[n]], 1);
    __syncthreads();
    if (tid < 256) { int s = 0; for (int i = 0; i < 8; i++) s += cnt[tid * 8 + i]; part[tid] = s; }
    __syncthreads();
    if (tid == 0) {
        int run = 0;
        for (int i = 0; i < 256; i++) { int v = part[i]; part[i] = run; run += v; }
    }
    if (tid < 16) {                            // per-tree level prefix + maxlev
        int run = 0, mx = 1;
        for (int l = 0; l < 32; l++) {
            loff[tid * 32 + l] = tid * 128 + run;
            if (lvl[tid * 32 + l] > 0) mx = l;
            run += lvl[tid * 32 + l];
        }
        g_tmax[tid] = mx;
    }
    __syncthreads();
    for (int i = tid; i < 512; i += 1024) g_tl_off[i] = loff[i];
    if (tid < 256) {
        int run = part[tid];
        for (int i = 0; i < 8; i++) { int idx = tid * 8 + i; g_coff[idx] = run; run += cnt[idx]; }
        if (tid == 255) g_coff[Nn] = run;
    }
    __syncthreads();
    // deterministic CSR scatter: rank = #earlier same-parent edges (same batch)
    for (int e = tid; e < Ev; e += 1024) {
        int p = psm[e];
        int bstart = (e / (Sv - 1)) * (Sv - 1);
        int rank = 0;
        for (int e2 = bstart; e2 < e; e2++) rank += (psm[e2] == p);
        g_children[g_coff[p] + rank] = child_idx[e];
    }
    // per-tree level bucket fill (intra-level order numerically irrelevant)
    for (int n = tid; n < Nn; n += 1024) {
        int key = (n >> 7) * 32 + hsm[n];
        int r = atomicAdd(&lfill[key], 1);
        g_tl_nodes[loff[key] + r] = n;
    }
}

// ---------------- persistent kernel: per-tree clusters --------------------
__global__ void __launch_bounds__(NTHR, 1) __cluster_dims__(8, 1, 1)
main_kernel(const int* __restrict__ xs, const int* __restrict__ rels,
            const float* __restrict__ emb_W, const float* __restrict__ rel_W,
            const float* __restrict__ W_ix, const float* __restrict__ b_ix,
            const float* __restrict__ W_ih, const float* __restrict__ b_ih,
            const float* __restrict__ W_fx, const float* __restrict__ b_fx,
            const float* __restrict__ W_fh, const float* __restrict__ b_fh,
            const float* __restrict__ W_ox, const float* __restrict__ W_oh,
            const float* __restrict__ W_ux, const float* __restrict__ W_uh,
            const float* __restrict__ W_out, const float* __restrict__ b_out,
            float* __restrict__ out) {
    extern __shared__ float sm[];
    // P1: sm[0..32768) = 256x128 input-weight slice, layout [k/4][c*4 + k%4]
    // P3: same region re-used as 4 recurrent 256x32 slices
    float* Wih4 = sm;
    float* Woh4 = sm + 8192;
    float* Wuh4 = sm + 16384;
    float* Wfh4 = sm + 24576;
    float* scratch = sm + 32768;      // 16384 floats

    const int tid  = threadIdx.x;
    const int lane = tid & 31;
    const int warp = tid >> 5;
    const int blk  = blockIdx.x;
    const int b    = blk >> 3;        // tree id (cluster id)
    const int g    = blk & 7;         // column group (rank in cluster)

    // ---- P1: input projections for this tree's 128 nodes, cols [.,+128) --
    {
        const float* mats[4] = {W_ix, W_fx, W_ox, W_ux};
        const float* Wsel = mats[g >> 1];
        const int colbase = (g & 1) * 128;
        float* Wsm = sm;
        for (int idx = tid; idx < 32768; idx += NTHR) {
            int k = idx >> 7, c = idx & 127;
            Wsm[(k >> 2) * 512 + c * 4 + (k & 3)] = Wsel[k * Hv + colbase + c];
        }
        __syncthreads();
        const int matid = g >> 1;
        float* dst = g_proj[matid];
        float* x4 = scratch + warp * 1024;
        for (int t = 0; t < 2; t++) {
            int ng = warp * 2 + t;              // 0..31 node groups of 4
            int nb = b * Sv + ng * 4;           // global node base
            __syncwarp();
            #pragma unroll
            for (int m = 0; m < 4; m++) {
                int n = nb + m;
                const float4* er = (const float4*)(emb_W + (size_t)xs[n] * DEv);
                const float4* rr = (const float4*)(rel_W + (size_t)rels[n] * DRv);
                float4 a = er[lane];
                float4 bb = (lane < 16) ? er[lane + 32] : rr[lane - 16];
                float4* dm = (float4*)(x4 + m * 256);
                dm[lane] = a; dm[lane + 32] = bb;
            }
            __syncwarp();
            for (int cg = 0; cg < 4; cg++) {
                unsigned long long accA[4] = {0,0,0,0}, accB[4] = {0,0,0,0};
                const float* wp = Wsm + (cg * 32 + lane) * 4;
                #pragma unroll 4
                for (int k4 = 0; k4 < 64; k4++) {
                    ulonglong2 wv = *(const ulonglong2*)(wp + k4 * 512);
                    #pragma unroll
                    for (int m = 0; m < 4; m++) {
                        ulonglong2 xv = *(const ulonglong2*)&x4[m * 256 + k4 * 4];
                        FFMA2(accA[m], xv.x, wv.x);
                        FFMA2(accB[m], xv.y, wv.y);
                    }
                }
                int colm = colbase + cg * 32 + lane;
                float bias = 0.0f;
                if (matid == 0)      bias = b_ix[colm] + b_ih[colm];
                else if (matid == 1) bias = b_fx[colm] + b_fh[colm];
                #pragma unroll
                for (int m = 0; m < 4; m++)
                    dst[(size_t)(nb + m) * Hv + colm] =
                        pairsum(accA[m]) + pairsum(accB[m]) + bias;
            }
        }
        __syncthreads();
        // load recurrent weight slices (overwrite Wsm region)
        const int jb2 = g * 32;
        for (int it = 0; it < 16; it++) {
            int k = it * 16 + (tid >> 5);
            int col = tid & 31;
            int didx = (k >> 2) * 128 + col * 4 + (k & 3);
            int sidx = k * Hv + jb2 + col;
            Wih4[didx] = W_ih[sidx];
            Woh4[didx] = W_oh[sidx];
            Wuh4[didx] = W_uh[sidx];
            Wfh4[didx] = W_fh[sidx];
        }
    }
    cluster_bar();

    const int J = g * 32 + lane;

    // ---- P2: leaves (level 0): elementwise, column-partitioned ------------
    {
        int base0 = g_tl_off[b * 32];
        int cnt0  = g_tl_off[b * 32 + 1] - base0;
        for (int idx = warp; idx < cnt0; idx += 16) {
            int n = g_tl_nodes[base0 + idx];
            #pragma unroll
            for (int q = 0; q < 1; q++) { }
            size_t ix0 = (size_t)n * Hv + J;
            float iv = sigf(g_proj[0][ix0]);
            float ov = sigf(g_proj[2][ix0]);
            float uv = __tanhf(g_proj[3][ix0]);
            float cv = iv * uv;
            g_c[ix0] = cv;
            g_h[ix0] = ov * __tanhf(cv);
        }
    }
    cluster_bar();

    // ---- P3: bottom-up levels; fh-phase + gate-phase per level -----------
    {
        const int tmax = g_tmax[b];
        float* hb = scratch + warp * 512;
        float* cb = hb + 256;

        for (int lev = 1; lev <= tmax; lev++) {
            // (a) fh-phase: fh = W_fh . h for nodes of level lev-1
            {
                int pbase = g_tl_off[b * 32 + (lev - 1)];
                int pcnt  = g_tl_off[b * 32 + lev] - pbase;
                for (int idx = warp; idx < pcnt; idx += 16) {
                    int n = g_tl_nodes[pbase + idx];
                    __syncwarp();
                    const float4* hsrc = (const float4*)(g_h + (size_t)n * Hv);
                    float4 v0 = hsrc[lane], v1 = hsrc[lane + 32];
                    float4* cbv = (float4*)cb;
                    cbv[lane] = v0; cbv[lane + 32] = v1;
                    __syncwarp();
                    unsigned long long fA = 0, fB = 0, fC = 0, fD = 0;
                    #pragma unroll 8
                    for (int k4 = 0; k4 < 64; k4 += 2) {
                        ulonglong2 cv0 = *(const ulonglong2*)&cb[k4 * 4];
                        ulonglong2 wf0 = *(const ulonglong2*)&Wfh4[k4 * 128 + lane * 4];
                        ulonglong2 cv1 = *(const ulonglong2*)&cb[k4 * 4 + 4];
                        ulonglong2 wf1 = *(const ulonglong2*)&Wfh4[k4 * 128 + 128 + lane * 4];
                        FFMA2(fA, cv0.x, wf0.x);
                        FFMA2(fB, cv0.y, wf0.y);
                        FFMA2(fC, cv1.x, wf1.x);
                        FFMA2(fD, cv1.y, wf1.y);
                    }
                    g_fh[(size_t)n * Hv + J] =
                        (pairsum(fA) + pairsum(fB)) + (pairsum(fC) + pairsum(fD));
                }
            }
            __syncthreads();   // fh (column-local) visible to CTA's gate-phase

            // (b) gate-phase: nodes of level lev
            {
                int base = g_tl_off[b * 32 + lev];
                int cnt  = g_tl_off[b * 32 + lev + 1] - base;
                for (int idx = warp; idx < cnt; idx += 16) {
                    int n = g_tl_nodes[base + idx];
                    float fxv = g_proj[1][(size_t)n * Hv + J];
                    int cs = g_coff[n], ce = g_coff[n + 1];
                    float4 s0 = make_float4(0,0,0,0), s1 = make_float4(0,0,0,0);
                    float fc = 0.0f;
                    for (int ci = cs; ci < ce; ci++) {
                        int ch = g_children[ci];
                        const float4* hsrc = (const float4*)(g_h + (size_t)ch * Hv);
                        float4 v0 = hsrc[lane], v1 = hsrc[lane + 32];
                        s0.x += v0.x; s0.y += v0.y; s0.z += v0.z; s0.w += v0.w;
                        s1.x += v1.x; s1.y += v1.y; s1.z += v1.z; s1.w += v1.w;
                        float fhv = g_fh[(size_t)ch * Hv + J];
                        float cch = g_c[(size_t)ch * Hv + J];
                        fc += sigf(fhv + fxv) * cch;
                    }
                    __syncwarp();
                    float4* hbv = (float4*)hb;
                    hbv[lane] = s0; hbv[lane + 32] = s1;
                    __syncwarp();
                    unsigned long long iA = 0, iB = 0, oA = 0, oB = 0, uA = 0, uB = 0;
                    #pragma unroll 4
                    for (int k4 = 0; k4 < 64; k4++) {
                        ulonglong2 hv = *(const ulonglong2*)&hb[k4 * 4];
                        ulonglong2 wi = *(const ulonglong2*)&Wih4[k4 * 128 + lane * 4];
                        ulonglong2 wo = *(const ulonglong2*)&Woh4[k4 * 128 + lane * 4];
                        ulonglong2 wu = *(const ulonglong2*)&Wuh4[k4 * 128 + lane * 4];
                        FFMA2(iA, hv.x, wi.x); FFMA2(iB, hv.y, wi.y);
                        FFMA2(oA, hv.x, wo.x); FFMA2(oB, hv.y, wo.y);
                        FFMA2(uA, hv.x, wu.x); FFMA2(uB, hv.y, wu.y);
                    }
                    size_t nidx = (size_t)n * Hv + J;
                    float iv = sigf(g_proj[0][nidx] + pairsum(iA) + pairsum(iB));
                    float ov = sigf(g_proj[2][nidx] + pairsum(oA) + pairsum(oB));
                    float uv = __tanhf(g_proj[3][nidx] + pairsum(uA) + pairsum(uB));
                    float cn = iv * uv + fc;
                    g_c[nidx] = cn;
                    g_h[nidx] = ov * __tanhf(cn);
                }
            }
            cluster_bar();
        }
    }

    // ---- P4: per-tree max-pool + output head ------------------------------
    {
        int col = g * 32 + lane;
        float m = -1e30f;
        for (int s = warp; s < Sv; s += 16)
            m = fmaxf(m, g_h[(size_t)(b * Sv + s) * Hv + col]);
        scratch[warp * 32 + lane] = m;
        __syncthreads();
        if (tid < 32) {
            float mm = scratch[tid];
            #pragma unroll
            for (int r = 1; r < 16; r++) mm = fmaxf(mm, scratch[r * 32 + tid]);
            g_pooled[b * Hv + g * 32 + tid] = mm;
        }
    }
    cluster_bar();
    if (g == 0 && warp < Lv) {
        float acc = 0.0f;
        for (int k = lane; k < Hv; k += 32)
            acc += g_pooled[b * Hv + k] * W_out[k * Lv + warp];
        #pragma unroll
        for (int off = 16; off; off >>= 1)
            acc += __shfl_down_sync(0xFFFFFFFFu, acc, off);
        if (lane == 0) out[b * Lv + warp] = acc + b_out[warp];
    }
}

// ---------------- launch --------------------------------------------------
extern "C" void kernel_launch(void* const* d_in, const int* in_sizes, int n_in,
                              void* d_out, int out_size) {
    const int s = (n_in >= 22) ? 1 : 0;   // robust to n_levels scalar presence
    const int* xs          = (const int*)d_in[0];
    const int* rels        = (const int*)d_in[1];
    const int* child_idx   = (const int*)d_in[2];
    const int* parent_idx  = (const int*)d_in[3];
    const int* node_height = (const int*)d_in[4];
    const float* emb_W = (const float*)d_in[5 + s];
    const float* rel_W = (const float*)d_in[6 + s];
    const float* W_ix  = (const float*)d_in[7 + s];
    const float* b_ix  = (const float*)d_in[8 + s];
    const float* W_ih  = (const float*)d_in[9 + s];
    const float* b_ih  = (const float*)d_in[10 + s];
    const float* W_fx  = (const float*)d_in[11 + s];
    const float* b_fx  = (const float*)d_in[12 + s];
    const float* W_fh  = (const float*)d_in[13 + s];
    const float* b_fh  = (const float*)d_in[14 + s];
    const float* W_ox  = (const float*)d_in[15 + s];
    const float* W_oh  = (const float*)d_in[16 + s];
    const float* W_ux  = (const float*)d_in[17 + s];
    const float* W_uh  = (const float*)d_in[18 + s];
    const float* W_out = (const float*)d_in[19 + s];
    const float* b_out = (const float*)d_in[20 + s];
    float* out = (float*)d_out;

    cudaFuncSetAttribute(main_kernel, cudaFuncAttributeMaxDynamicSharedMemorySize, SMEM_BYTES);

    setup_kernel<<<1, 1024>>>(child_idx, parent_idx, node_height);
    main_kernel<<<NCTA, NTHR, SMEM_BYTES>>>(xs, rels, emb_W, rel_W,
                                            W_ix, b_ix, W_ih, b_ih,
                                            W_fx, b_fx, W_fh, b_fh,
                                            W_ox, W_oh, W_ux, W_uh,
                                            W_out, b_out, out);
}

// round 5
// speedup vs baseline: 1.4895x; 1.4895x over previous
#include <cuda_runtime.h>

#define Nn   2048      // B*S
#define Bv   16
#define Sv   128
#define Hv   256
#define DINv 256
#define DEv  192
#define DRv  64
#define Ev   2032      // B*(S-1)
#define Lv   12
#define NCTA 128       // 16 trees x 8 column groups
#define NTHR 512
#define SMEM_BYTES 196608   // 48K floats: 32K weights + 16K scratch

// packed fp32x2 FMA (sm_103a FFMA2)
#define FFMA2(acc, a, b) asm("fma.rn.f32x2 %0, %1, %2, %0;" : "+l"(acc) : "l"(a), "l"(b))

__device__ __forceinline__ float pairsum(unsigned long long v) {
    float lo, hi;
    asm("mov.b64 {%0, %1}, %2;" : "=f"(lo), "=f"(hi) : "l"(v));
    return lo + hi;
}

// ---------------- device scratch (no allocations allowed) ----------------
__device__ float g_proj[4][Nn * Hv];   // ix(+b_ix+b_ih), fx(+b_fx+b_fh), ox, ux
__device__ float g_h[Nn * Hv];
__device__ float g_c[Nn * Hv];
__device__ float g_fh[Nn * Hv];        // W_fh . h_n per node (col-local)
__device__ float g_pooled[Bv * Hv];
__device__ int   g_coff[Nn + 1];
__device__ int   g_children[Ev];
__device__ int   g_tl_off[512];        // [16][32] per-tree level offsets
__device__ int   g_tl_nodes[Nn];       // per-tree level-bucketed node ids
__device__ int   g_tmax[Bv];
__device__ unsigned g_tcnt[Bv * 32];   // per-tree barrier, 128B apart
__device__ unsigned g_tgen[Bv * 32];

// fence-free release/acquire primitives (no CCTL.IVALL -> L1 stays warm)
__device__ __forceinline__ unsigned ld_acq(unsigned* p) {
    unsigned v;
    asm volatile("ld.acquire.gpu.global.u32 %0, [%1];" : "=r"(v) : "l"(p) : "memory");
    return v;
}
__device__ __forceinline__ unsigned atom_add_rel(unsigned* p, unsigned v) {
    unsigned old;
    asm volatile("atom.release.gpu.global.add.u32 %0, [%1], %2;"
                 : "=r"(old) : "l"(p), "r"(v) : "memory");
    return old;
}
__device__ __forceinline__ void red_add_rel(unsigned* p, unsigned v) {
    asm volatile("red.release.gpu.global.add.u32 [%0], %1;" :: "l"(p), "r"(v) : "memory");
}

// per-tree barrier (8 CTAs), sense-reversal, release/acquire only
__device__ __forceinline__ void tree_bar(int b) {
    __syncthreads();
    if (threadIdx.x == 0) {
        unsigned* cntp = &g_tcnt[b * 32];
        unsigned* genp = &g_tgen[b * 32];
        unsigned gen = ld_acq(genp);             // snapshot BEFORE arriving
        unsigned t = atom_add_rel(cntp, 1u);     // release: my stores -> L2 first
        if (t == 7u) {
            *(volatile unsigned*)cntp = 0u;      // reset, ordered by release below
            red_add_rel(genp, 1u);               // publish
        } else {
            int it = 0;
            while (ld_acq(genp) == gen) { if (++it > 16) __nanosleep(32); }
        }
    }
    __syncthreads();
}

__device__ __forceinline__ float sigf(float x) {
    return 1.0f / (1.0f + __expf(-x));
}

// ---------------- setup: CSR of children + per-tree level buckets ---------
__global__ void setup_kernel(const int* __restrict__ child_idx,
                             const int* __restrict__ parent_idx,
                             const int* __restrict__ node_height) {
    __shared__ int cnt[Nn];
    __shared__ int psm[Ev];
    __shared__ int hsm[Nn];
    __shared__ int part[256];
    __shared__ int lvl[512];
    __shared__ int lfill[512];
    __shared__ int loff[512];
    const int tid = threadIdx.x;               // 1024 threads
    for (int i = tid; i < Nn; i += 1024) { cnt[i] = 0; hsm[i] = node_height[i]; }
    for (int i = tid; i < Ev; i += 1024) psm[i] = parent_idx[i];
    for (int i = tid; i < 512; i += 1024) { lvl[i] = 0; lfill[i] = 0; }
    __syncthreads();
    for (int e = tid; e < Ev; e += 1024) atomicAdd(&cnt[psm[e]], 1);
    for (int n = tid; n < Nn; n += 1024) atomicAdd(&lvl[(n >> 7) * 32 + hsm[n]], 1);
    __syncthreads();
    if (tid < 256) { int s = 0; for (int i = 0; i < 8; i++) s += cnt[tid * 8 + i]; part[tid] = s; }
    __syncthreads();
    if (tid == 0) {
        int run = 0;
        for (int i = 0; i < 256; i++) { int v = part[i]; part[i] = run; run += v; }
    }
    if (tid < 16) {                            // per-tree level prefix + maxlev
        int run = 0, mx = 1;
        for (int l = 0; l < 32; l++) {
            loff[tid * 32 + l] = tid * 128 + run;
            if (lvl[tid * 32 + l] > 0) mx = l;
            run += lvl[tid * 32 + l];
        }
        g_tmax[tid] = mx;
    }
    __syncthreads();
    for (int i = tid; i < 512; i += 1024) g_tl_off[i] = loff[i];
    if (tid < 256) {
        int run = part[tid];
        for (int i = 0; i < 8; i++) { int idx = tid * 8 + i; g_coff[idx] = run; run += cnt[idx]; }
        if (tid == 255) g_coff[Nn] = run;
    }
    __syncthreads();
    // deterministic CSR scatter: rank = #earlier same-parent edges (same batch)
    for (int e = tid; e < Ev; e += 1024) {
        int p = psm[e];
        int bstart = (e / (Sv - 1)) * (Sv - 1);
        int rank = 0;
        for (int e2 = bstart; e2 < e; e2++) rank += (psm[e2] == p);
        g_children[g_coff[p] + rank] = child_idx[e];
    }
    // per-tree level bucket fill (intra-level order numerically irrelevant)
    for (int n = tid; n < Nn; n += 1024) {
        int key = (n >> 7) * 32 + hsm[n];
        int r = atomicAdd(&lfill[key], 1);
        g_tl_nodes[loff[key] + r] = n;
    }
}

// ---------------- persistent kernel: per-tree asynchronous ----------------
__global__ void __launch_bounds__(NTHR, 1)
main_kernel(const int* __restrict__ xs, const int* __restrict__ rels,
            const float* __restrict__ emb_W, const float* __restrict__ rel_W,
            const float* __restrict__ W_ix, const float* __restrict__ b_ix,
            const float* __restrict__ W_ih, const float* __restrict__ b_ih,
            const float* __restrict__ W_fx, const float* __restrict__ b_fx,
            const float* __restrict__ W_fh, const float* __restrict__ b_fh,
            const float* __restrict__ W_ox, const float* __restrict__ W_oh,
            const float* __restrict__ W_ux, const float* __restrict__ W_uh,
            const float* __restrict__ W_out, const float* __restrict__ b_out,
            float* __restrict__ out) {
    extern __shared__ float sm[];
    float* Wih4 = sm;                 // P1 re-uses sm[0..32768) for Wx slice
    float* Woh4 = sm + 8192;
    float* Wuh4 = sm + 16384;
    float* Wfh4 = sm + 24576;
    float* scratch = sm + 32768;      // 16384 floats = 16 warps x 1024

    const int tid  = threadIdx.x;
    const int lane = tid & 31;
    const int warp = tid >> 5;
    const int blk  = blockIdx.x;
    const int b    = blk >> 3;        // tree id
    const int g    = blk & 7;         // column group

    // ---- P1: input projections for this tree's 128 nodes ----------------
    {
        const float* mats[4] = {W_ix, W_fx, W_ox, W_ux};
        const float* Wsel = mats[g >> 1];
        const int colbase = (g & 1) * 128;
        float* Wsm = sm;
        for (int idx = tid; idx < 32768; idx += NTHR) {
            int k = idx >> 7, c = idx & 127;
            Wsm[(k >> 2) * 512 + c * 4 + (k & 3)] = Wsel[k * Hv + colbase + c];
        }
        __syncthreads();
        const int matid = g >> 1;
        float* dst = g_proj[matid];
        float* x4 = scratch + warp * 1024;
        for (int t = 0; t < 2; t++) {
            int ng = warp * 2 + t;              // 0..31 node groups of 4
            int nb = b * Sv + ng * 4;
            __syncwarp();
            #pragma unroll
            for (int m = 0; m < 4; m++) {
                int n = nb + m;
                const float4* er = (const float4*)(emb_W + (size_t)xs[n] * DEv);
                const float4* rr = (const float4*)(rel_W + (size_t)rels[n] * DRv);
                float4 a = er[lane];
                float4 bb = (lane < 16) ? er[lane + 32] : rr[lane - 16];
                float4* dm = (float4*)(x4 + m * 256);
                dm[lane] = a; dm[lane + 32] = bb;
            }
            __syncwarp();
            for (int cg = 0; cg < 4; cg++) {
                unsigned long long acc[4] = {0,0,0,0};
                unsigned long long accB[4] = {0,0,0,0};
                const float* wp = Wsm + (cg * 32 + lane) * 4;
                #pragma unroll 4
                for (int k4 = 0; k4 < 64; k4++) {
                    ulonglong2 wv = *(const ulonglong2*)(wp + k4 * 512);
                    #pragma unroll
                    for (int m = 0; m < 4; m++) {
                        ulonglong2 xv = *(const ulonglong2*)&x4[m * 256 + k4 * 4];
                        FFMA2(acc[m], xv.x, wv.x);
                        FFMA2(accB[m], xv.y, wv.y);
                    }
                }
                int colm = colbase + cg * 32 + lane;
                float bias = 0.0f;
                if (matid == 0)      bias = b_ix[colm] + b_ih[colm];
                else if (matid == 1) bias = b_fx[colm] + b_fh[colm];
                #pragma unroll
                for (int m = 0; m < 4; m++)
                    dst[(size_t)(nb + m) * Hv + colm] =
                        pairsum(acc[m]) + pairsum(accB[m]) + bias;
            }
        }
        __syncthreads();
        // load recurrent weight slices (overwrite Wsm region)
        const int jb2 = g * 32;
        for (int it = 0; it < 16; it++) {
            int k = it * 16 + (tid >> 5);
            int col = tid & 31;
            int didx = (k >> 2) * 128 + col * 4 + (k & 3);
            int sidx = k * Hv + jb2 + col;
            Wih4[didx] = W_ih[sidx];
            Woh4[didx] = W_oh[sidx];
            Wuh4[didx] = W_uh[sidx];
            Wfh4[didx] = W_fh[sidx];
        }
    }
    tree_bar(b);

    const int J = g * 32 + lane;

    // ---- P2: leaves (level 0): elementwise, column-partitioned -----------
    {
        int base0 = g_tl_off[b * 32];
        int cnt0  = g_tl_off[b * 32 + 1] - base0;
        for (int idx = warp; idx < cnt0; idx += 16) {
            int n = g_tl_nodes[base0 + idx];
            size_t ix0 = (size_t)n * Hv + J;
            float iv = sigf(g_proj[0][ix0]);
            float ov = sigf(g_proj[2][ix0]);
            float uv = __tanhf(g_proj[3][ix0]);
            float cv = iv * uv;
            g_c[ix0] = cv;
            g_h[ix0] = ov * __tanhf(cv);
        }
    }
    tree_bar(b);

    // ---- P3: bottom-up levels; fh-phase + gate-phase per level -----------
    {
        const int tmax = g_tmax[b];
        float* hbw = scratch + warp * 1024;   // 4 nodes x 256

        for (int lev = 1; lev <= tmax; lev++) {
            // (a) fh-phase: fh = W_fh . h for nodes of height lev-1
            {
                int pbase = g_tl_off[b * 32 + (lev - 1)];
                int pcnt  = g_tl_off[b * 32 + lev] - pbase;
                for (int i0 = warp * 4; i0 < pcnt; i0 += 64) {
                    int mcount = pcnt - i0; if (mcount > 4) mcount = 4;
                    int nid[4];
                    __syncwarp();
                    #pragma unroll
                    for (int m = 0; m < 4; m++) {
                        if (m < mcount) {
                            int n = g_tl_nodes[pbase + i0 + m];
                            nid[m] = n;
                            const float4* hsrc = (const float4*)(g_h + (size_t)n * Hv);
                            float4* dm = (float4*)(hbw + m * 256);
                            dm[lane] = hsrc[lane];
                            dm[lane + 32] = hsrc[lane + 32];
                        } else nid[m] = -1;
                    }
                    __syncwarp();
                    if (mcount == 1) {
                        unsigned long long af = 0;
                        #pragma unroll 8
                        for (int k4 = 0; k4 < 64; k4++) {
                            ulonglong2 wf = *(const ulonglong2*)&Wfh4[k4 * 128 + lane * 4];
                            ulonglong2 xv = *(const ulonglong2*)&hbw[k4 * 4];
                            FFMA2(af, xv.x, wf.x);
                            FFMA2(af, xv.y, wf.y);
                        }
                        g_fh[(size_t)nid[0] * Hv + J] = pairsum(af);
                    } else {
                        unsigned long long af[4] = {0,0,0,0};
                        #pragma unroll 4
                        for (int k4 = 0; k4 < 64; k4++) {
                            ulonglong2 wf = *(const ulonglong2*)&Wfh4[k4 * 128 + lane * 4];
                            #pragma unroll
                            for (int m = 0; m < 4; m++) {
                                ulonglong2 xv = *(const ulonglong2*)&hbw[m * 256 + k4 * 4];
                                FFMA2(af[m], xv.x, wf.x);
                                FFMA2(af[m], xv.y, wf.y);
                            }
                        }
                        #pragma unroll
                        for (int m = 0; m < 4; m++)
                            if (nid[m] >= 0)
                                g_fh[(size_t)nid[m] * Hv + J] = pairsum(af[m]);
                    }
                }
            }
            __syncthreads();   // fh (column-local) visible to CTA's gate-phase

            // (b) gate-phase: nodes of height lev
            {
                int base = g_tl_off[b * 32 + lev];
                int cnt  = g_tl_off[b * 32 + lev + 1] - base;
                for (int i0 = warp * 4; i0 < cnt; i0 += 64) {
                    int mcount = cnt - i0; if (mcount > 4) mcount = 4;
                    int nid[4]; float fcv[4];
                    __syncwarp();
                    #pragma unroll
                    for (int m = 0; m < 4; m++) {
                        fcv[m] = 0.0f;
                        if (m < mcount) {
                            int n = g_tl_nodes[base + i0 + m];
                            nid[m] = n;
                            float fxv = g_proj[1][(size_t)n * Hv + J];
                            int cs = g_coff[n], ce = g_coff[n + 1];
                            float4 s0 = make_float4(0,0,0,0), s1 = make_float4(0,0,0,0);
                            float fc = 0.0f;
                            for (int ci = cs; ci < ce; ci++) {
                                int ch = g_children[ci];
                                const float4* hsrc = (const float4*)(g_h + (size_t)ch * Hv);
                                float4 v0 = hsrc[lane], v1 = hsrc[lane + 32];
                                s0.x += v0.x; s0.y += v0.y; s0.z += v0.z; s0.w += v0.w;
                                s1.x += v1.x; s1.y += v1.y; s1.z += v1.z; s1.w += v1.w;
                                fc += sigf(g_fh[(size_t)ch * Hv + J] + fxv)
                                      * g_c[(size_t)ch * Hv + J];
                            }
                            float4* dm = (float4*)(hbw + m * 256);
                            dm[lane] = s0; dm[lane + 32] = s1;
                            fcv[m] = fc;
                        } else nid[m] = -1;
                    }
                    __syncwarp();
                    if (mcount == 1) {
                        unsigned long long ai = 0, ao = 0, au = 0;
                        #pragma unroll 4
                        for (int k4 = 0; k4 < 64; k4++) {
                            ulonglong2 xv = *(const ulonglong2*)&hbw[k4 * 4];
                            ulonglong2 wi = *(const ulonglong2*)&Wih4[k4 * 128 + lane * 4];
                            ulonglong2 wo = *(const ulonglong2*)&Woh4[k4 * 128 + lane * 4];
                            ulonglong2 wu = *(const ulonglong2*)&Wuh4[k4 * 128 + lane * 4];
                            FFMA2(ai, xv.x, wi.x); FFMA2(ai, xv.y, wi.y);
                            FFMA2(ao, xv.x, wo.x); FFMA2(ao, xv.y, wo.y);
                            FFMA2(au, xv.x, wu.x); FFMA2(au, xv.y, wu.y);
                        }
                        size_t nidx = (size_t)nid[0] * Hv + J;
                        float iv = sigf(g_proj[0][nidx] + pairsum(ai));
                        float ov = sigf(g_proj[2][nidx] + pairsum(ao));
                        float uv = __tanhf(g_proj[3][nidx] + pairsum(au));
                        float cn = iv * uv + fcv[0];
                        g_c[nidx] = cn;
                        g_h[nidx] = ov * __tanhf(cn);
                    } else {
                        unsigned long long ai[4] = {0,0,0,0};
                        unsigned long long ao[4] = {0,0,0,0};
                        unsigned long long au[4] = {0,0,0,0};
                        #pragma unroll 2
                        for (int k4 = 0; k4 < 64; k4++) {
                            ulonglong2 wi = *(const ulonglong2*)&Wih4[k4 * 128 + lane * 4];
                            ulonglong2 wo = *(const ulonglong2*)&Woh4[k4 * 128 + lane * 4];
                            ulonglong2 wu = *(const ulonglong2*)&Wuh4[k4 * 128 + lane * 4];
                            #pragma unroll
                            for (int m = 0; m < 4; m++) {
                                ulonglong2 xv = *(const ulonglong2*)&hbw[m * 256 + k4 * 4];
                                FFMA2(ai[m], xv.x, wi.x); FFMA2(ai[m], xv.y, wi.y);
                                FFMA2(ao[m], xv.x, wo.x); FFMA2(ao[m], xv.y, wo.y);
                                FFMA2(au[m], xv.x, wu.x); FFMA2(au[m], xv.y, wu.y);
                            }
                        }
                        #pragma unroll
                        for (int m = 0; m < 4; m++) {
                            if (nid[m] < 0) continue;
                            size_t nidx = (size_t)nid[m] * Hv + J;
                            float iv = sigf(g_proj[0][nidx] + pairsum(ai[m]));
                            float ov = sigf(g_proj[2][nidx] + pairsum(ao[m]));
                            float uv = __tanhf(g_proj[3][nidx] + pairsum(au[m]));
                            float cn = iv * uv + fcv[m];
                            g_c[nidx] = cn;
                            g_h[nidx] = ov * __tanhf(cn);
                        }
                    }
                }
            }
            tree_bar(b);
        }
    }

    // ---- P4: per-tree max-pool + output head ------------------------------
    {
        int col = g * 32 + lane;
        float m = -1e30f;
        for (int s = warp; s < Sv; s += 16)
            m = fmaxf(m, g_h[(size_t)(b * Sv + s) * Hv + col]);
        scratch[warp * 32 + lane] = m;
        __syncthreads();
        if (tid < 32) {
            float mm = scratch[tid];
            #pragma unroll
            for (int r = 1; r < 16; r++) mm = fmaxf(mm, scratch[r * 32 + tid]);
            g_pooled[b * Hv + g * 32 + tid] = mm;
        }
    }
    tree_bar(b);
    if (g == 0 && warp < Lv) {
        float acc = 0.0f;
        for (int k = lane; k < Hv; k += 32)
            acc += g_pooled[b * Hv + k] * W_out[k * Lv + warp];
        #pragma unroll
        for (int off = 16; off; off >>= 1)
            acc += __shfl_down_sync(0xFFFFFFFFu, acc, off);
        if (lane == 0) out[b * Lv + warp] = acc + b_out[warp];
    }
}

// ---------------- launch --------------------------------------------------
extern "C" void kernel_launch(void* const* d_in, const int* in_sizes, int n_in,
                              void* d_out, int out_size) {
    const int s = (n_in >= 22) ? 1 : 0;   // robust to n_levels scalar presence
    const int* xs          = (const int*)d_in[0];
    const int* rels        = (const int*)d_in[1];
    const int* child_idx   = (const int*)d_in[2];
    const int* parent_idx  = (const int*)d_in[3];
    const int* node_height = (const int*)d_in[4];
    const float* emb_W = (const float*)d_in[5 + s];
    const float* rel_W = (const float*)d_in[6 + s];
    const float* W_ix  = (const float*)d_in[7 + s];
    const float* b_ix  = (const float*)d_in[8 + s];
    const float* W_ih  = (const float*)d_in[9 + s];
    const float* b_ih  = (const float*)d_in[10 + s];
    const float* W_fx  = (const float*)d_in[11 + s];
    const float* b_fx  = (const float*)d_in[12 + s];
    const float* W_fh  = (const float*)d_in[13 + s];
    const float* b_fh  = (const float*)d_in[14 + s];
    const float* W_ox  = (const float*)d_in[15 + s];
    const float* W_oh  = (const float*)d_in[16 + s];
    const float* W_ux  = (const float*)d_in[17 + s];
    const float* W_uh  = (const float*)d_in[18 + s];
    const float* W_out = (const float*)d_in[19 + s];
    const float* b_out = (const float*)d_in[20 + s];
    float* out = (float*)d_out;

    cudaFuncSetAttribute(main_kernel, cudaFuncAttributeMaxDynamicSharedMemorySize, SMEM_BYTES);

    setup_kernel<<<1, 1024>>>(child_idx, parent_idx, node_height);
    main_kernel<<<NCTA, NTHR, SMEM_BYTES>>>(xs, rels, emb_W, rel_W,
                                            W_ix, b_ix, W_ih, b_ih,
                                            W_fx, b_fx, W_fh, b_fh,
                                            W_ox, W_oh, W_ux, W_uh,
                                            W_out, b_out, out);
}

// round 6
// speedup vs baseline: 1.6699x; 1.1211x over previous
#include <cuda_runtime.h>

#define Nn   2048      // B*S
#define Bv   16
#define Sv   128
#define Hv   256
#define DINv 256
#define DEv  192
#define DRv  64
#define Ev   2032      // B*(S-1)
#define Lv   12
#define NCTA 128       // 16 trees x 8 column groups
#define NTHR 512
#define SMEM_BYTES 196608   // 48K floats: 32K weights + 16K scratch

// packed fp32x2 FMA (sm_103a FFMA2)
#define FFMA2(acc, a, b) asm("fma.rn.f32x2 %0, %1, %2, %0;" : "+l"(acc) : "l"(a), "l"(b))

__device__ __forceinline__ float pairsum(unsigned long long v) {
    float lo, hi;
    asm("mov.b64 {%0, %1}, %2;" : "=f"(lo), "=f"(hi) : "l"(v));
    return lo + hi;
}

// ---------------- device scratch (no allocations allowed) ----------------
__device__ float g_proj[4][Nn * Hv];   // ix(+b_ix+b_ih), fx(+b_fx+b_fh), ox, ux
__device__ float g_h[Nn * Hv];
__device__ float g_c[Nn * Hv];
__device__ float g_fh[Nn * Hv];        // W_fh . h_n per node (col-local)
__device__ float g_pooled[Bv * Hv];
__device__ int   g_coff[Nn + 1];
__device__ int   g_children[Ev];
__device__ int   g_tl_off[512];        // [16][32] per-tree level offsets
__device__ int   g_tl_nodes[Nn];       // per-tree level-bucketed node ids
__device__ int   g_tmax[Bv];
__device__ unsigned g_tcnt[Bv * 32];   // per-tree barrier, 128B apart
__device__ unsigned g_tgen[Bv * 32];

// fence-free release/acquire primitives (no CCTL.IVALL -> L1 stays warm)
__device__ __forceinline__ unsigned ld_acq(unsigned* p) {
    unsigned v;
    asm volatile("ld.acquire.gpu.global.u32 %0, [%1];" : "=r"(v) : "l"(p) : "memory");
    return v;
}
__device__ __forceinline__ unsigned ld_rlx(unsigned* p) {
    unsigned v;
    asm volatile("ld.relaxed.gpu.global.u32 %0, [%1];" : "=r"(v) : "l"(p) : "memory");
    return v;
}
__device__ __forceinline__ unsigned atom_add_rel(unsigned* p, unsigned v) {
    unsigned old;
    asm volatile("atom.release.gpu.global.add.u32 %0, [%1], %2;"
                 : "=r"(old) : "l"(p), "r"(v) : "memory");
    return old;
}
__device__ __forceinline__ void red_add_rel(unsigned* p, unsigned v) {
    asm volatile("red.release.gpu.global.add.u32 [%0], %1;" :: "l"(p), "r"(v) : "memory");
}
__device__ __forceinline__ void st_rlx(unsigned* p, unsigned v) {
    asm volatile("st.relaxed.gpu.global.u32 [%0], %1;" :: "l"(p), "r"(v) : "memory");
}

// per-tree barrier (8 CTAs), sense-reversal, release/acquire, PURE SPIN
// (no __nanosleep: its sleep quantum is far coarser than requested and adds
//  multi-us wakeup latency per level -- the R1..R5 hidden tax)
__device__ __forceinline__ void tree_bar(int b) {
    __syncthreads();
    if (threadIdx.x == 0) {
        unsigned* cntp = &g_tcnt[b * 32];
        unsigned* genp = &g_tgen[b * 32];
        unsigned gen = ld_rlx(genp);             // snapshot BEFORE arriving
        unsigned t = atom_add_rel(cntp, 1u);     // release: my stores -> L2 first
        if (t == 7u) {
            st_rlx(cntp, 0u);                    // reset; ordered by release below
            red_add_rel(genp, 1u);               // publish
        } else {
            while (ld_acq(genp) == gen) { }      // pure spin, ~250cyc/poll
        }
    }
    __syncthreads();
}

__device__ __forceinline__ float sigf(float x) {
    return 1.0f / (1.0f + __expf(-x));
}

// ---------------- setup: CSR of children + per-tree level buckets ---------
__global__ void setup_kernel(const int* __restrict__ child_idx,
                             const int* __restrict__ parent_idx,
                             const int* __restrict__ node_height) {
    __shared__ int cnt[Nn];
    __shared__ int psm[Ev];
    __shared__ int hsm[Nn];
    __shared__ int part[256];
    __shared__ int lvl[512];
    __shared__ int lfill[512];
    __shared__ int loff[512];
    const int tid = threadIdx.x;               // 1024 threads
    for (int i = tid; i < Nn; i += 1024) { cnt[i] = 0; hsm[i] = node_height[i]; }
    for (int i = tid; i < Ev; i += 1024) psm[i] = parent_idx[i];
    for (int i = tid; i < 512; i += 1024) { lvl[i] = 0; lfill[i] = 0; }
    __syncthreads();
    for (int e = tid; e < Ev; e += 1024) atomicAdd(&cnt[psm[e]], 1);
    for (int n = tid; n < Nn; n += 1024) atomicAdd(&lvl[(n >> 7) * 32 + hsm[n]], 1);
    __syncthreads();
    if (tid < 256) { int s = 0; for (int i = 0; i < 8; i++) s += cnt[tid * 8 + i]; part[tid] = s; }
    __syncthreads();
    if (tid == 0) {
        int run = 0;
        for (int i = 0; i < 256; i++) { int v = part[i]; part[i] = run; run += v; }
    }
    if (tid < 16) {                            // per-tree level prefix + maxlev
        int run = 0, mx = 1;
        for (int l = 0; l < 32; l++) {
            loff[tid * 32 + l] = tid * 128 + run;
            if (lvl[tid * 32 + l] > 0) mx = l;
            run += lvl[tid * 32 + l];
        }
        g_tmax[tid] = mx;
    }
    __syncthreads();
    for (int i = tid; i < 512; i += 1024) g_tl_off[i] = loff[i];
    if (tid < 256) {
        int run = part[tid];
        for (int i = 0; i < 8; i++) { int idx = tid * 8 + i; g_coff[idx] = run; run += cnt[idx]; }
        if (tid == 255) g_coff[Nn] = run;
    }
    __syncthreads();
    // deterministic CSR scatter: rank = #earlier same-parent edges (same batch)
    for (int e = tid; e < Ev; e += 1024) {
        int p = psm[e];
        int bstart = (e / (Sv - 1)) * (Sv - 1);
        int rank = 0;
        for (int e2 = bstart; e2 < e; e2++) rank += (psm[e2] == p);
        g_children[g_coff[p] + rank] = child_idx[e];
    }
    // per-tree level bucket fill (intra-level order numerically irrelevant)
    for (int n = tid; n < Nn; n += 1024) {
        int key = (n >> 7) * 32 + hsm[n];
        int r = atomicAdd(&lfill[key], 1);
        g_tl_nodes[loff[key] + r] = n;
    }
}

// ---------------- persistent kernel: per-tree asynchronous ----------------
__global__ void __launch_bounds__(NTHR, 1)
main_kernel(const int* __restrict__ xs, const int* __restrict__ rels,
            const float* __restrict__ emb_W, const float* __restrict__ rel_W,
            const float* __restrict__ W_ix, const float* __restrict__ b_ix,
            const float* __restrict__ W_ih, const float* __restrict__ b_ih,
            const float* __restrict__ W_fx, const float* __restrict__ b_fx,
            const float* __restrict__ W_fh, const float* __restrict__ b_fh,
            const float* __restrict__ W_ox, const float* __restrict__ W_oh,
            const float* __restrict__ W_ux, const float* __restrict__ W_uh,
            const float* __restrict__ W_out, const float* __restrict__ b_out,
            float* __restrict__ out) {
    extern __shared__ float sm[];
    float* Wih4 = sm;                 // P1 re-uses sm[0..32768) for Wx slice
    float* Woh4 = sm + 8192;
    float* Wuh4 = sm + 16384;
    float* Wfh4 = sm + 24576;
    float* scratch = sm + 32768;      // 16384 floats = 16 warps x 1024

    const int tid  = threadIdx.x;
    const int lane = tid & 31;
    const int warp = tid >> 5;
    const int blk  = blockIdx.x;
    const int b    = blk >> 3;        // tree id
    const int g    = blk & 7;         // column group

    // ---- P1: input projections for this tree's 128 nodes ----------------
    {
        const float* mats[4] = {W_ix, W_fx, W_ox, W_ux};
        const float* Wsel = mats[g >> 1];
        const int colbase = (g & 1) * 128;
        float* Wsm = sm;
        for (int idx = tid; idx < 32768; idx += NTHR) {
            int k = idx >> 7, c = idx & 127;
            Wsm[(k >> 2) * 512 + c * 4 + (k & 3)] = Wsel[k * Hv + colbase + c];
        }
        __syncthreads();
        const int matid = g >> 1;
        float* dst = g_proj[matid];
        float* x4 = scratch + warp * 1024;
        float biasv[4];
        #pragma unroll
        for (int cg = 0; cg < 4; cg++) {
            int colm = colbase + cg * 32 + lane;
            biasv[cg] = (matid == 0) ? (b_ix[colm] + b_ih[colm])
                      : (matid == 1) ? (b_fx[colm] + b_fh[colm]) : 0.0f;
        }
        for (int t = 0; t < 2; t++) {
            int nb = b * Sv + (warp * 2 + t) * 4;
            __syncwarp();
            #pragma unroll
            for (int m = 0; m < 4; m++) {
                int n = nb + m;
                const float4* er = (const float4*)(emb_W + (size_t)xs[n] * DEv);
                const float4* rr = (const float4*)(rel_W + (size_t)rels[n] * DRv);
                float4 a = er[lane];
                float4 bb = (lane < 16) ? er[lane + 32] : rr[lane - 16];
                float4* dm = (float4*)(x4 + m * 256);
                dm[lane] = a; dm[lane + 32] = bb;
            }
            __syncwarp();
            // k4-outer: x loaded once per k4, reused across all 4 col groups
            unsigned long long acc[4][4];
            #pragma unroll
            for (int m = 0; m < 4; m++)
                #pragma unroll
                for (int cg = 0; cg < 4; cg++) acc[m][cg] = 0ull;
            #pragma unroll 4
            for (int k4 = 0; k4 < 64; k4++) {
                ulonglong2 xv0 = *(const ulonglong2*)&x4[0 * 256 + k4 * 4];
                ulonglong2 xv1 = *(const ulonglong2*)&x4[1 * 256 + k4 * 4];
                ulonglong2 xv2 = *(const ulonglong2*)&x4[2 * 256 + k4 * 4];
                ulonglong2 xv3 = *(const ulonglong2*)&x4[3 * 256 + k4 * 4];
                #pragma unroll
                for (int cg = 0; cg < 4; cg++) {
                    ulonglong2 wv = *(const ulonglong2*)&Wsm[k4 * 512 + (cg * 32 + lane) * 4];
                    FFMA2(acc[0][cg], xv0.x, wv.x); FFMA2(acc[0][cg], xv0.y, wv.y);
                    FFMA2(acc[1][cg], xv1.x, wv.x); FFMA2(acc[1][cg], xv1.y, wv.y);
                    FFMA2(acc[2][cg], xv2.x, wv.x); FFMA2(acc[2][cg], xv2.y, wv.y);
                    FFMA2(acc[3][cg], xv3.x, wv.x); FFMA2(acc[3][cg], xv3.y, wv.y);
                }
            }
            #pragma unroll
            for (int cg = 0; cg < 4; cg++) {
                int colm = colbase + cg * 32 + lane;
                #pragma unroll
                for (int m = 0; m < 4; m++)
                    dst[(size_t)(nb + m) * Hv + colm] = pairsum(acc[m][cg]) + biasv[cg];
            }
        }
        __syncthreads();
        // load recurrent weight slices (overwrite Wsm region)
        const int jb2 = g * 32;
        for (int it = 0; it < 16; it++) {
            int k = it * 16 + (tid >> 5);
            int col = tid & 31;
            int didx = (k >> 2) * 128 + col * 4 + (k & 3);
            int sidx = k * Hv + jb2 + col;
            Wih4[didx] = W_ih[sidx];
            Woh4[didx] = W_oh[sidx];
            Wuh4[didx] = W_uh[sidx];
            Wfh4[didx] = W_fh[sidx];
        }
    }
    tree_bar(b);

    const int J = g * 32 + lane;

    // ---- P2: leaves (level 0): elementwise, column-partitioned -----------
    {
        int base0 = g_tl_off[b * 32];
        int cnt0  = g_tl_off[b * 32 + 1] - base0;
        for (int idx = warp; idx < cnt0; idx += 16) {
            int n = g_tl_nodes[base0 + idx];
            size_t ix0 = (size_t)n * Hv + J;
            float iv = sigf(g_proj[0][ix0]);
            float ov = sigf(g_proj[2][ix0]);
            float uv = __tanhf(g_proj[3][ix0]);
            float cv = iv * uv;
            g_c[ix0] = cv;
            g_h[ix0] = ov * __tanhf(cv);
        }
    }
    tree_bar(b);

    // ---- P3: bottom-up levels; fh-phase + gate-phase per level -----------
    {
        const int tmax = g_tmax[b];
        float* hbw = scratch + warp * 1024;   // 4 nodes x 256

        for (int lev = 1; lev <= tmax; lev++) {
            // (a) fh-phase: fh = W_fh . h for nodes of height lev-1
            {
                int pbase = g_tl_off[b * 32 + (lev - 1)];
                int pcnt  = g_tl_off[b * 32 + lev] - pbase;
                for (int i0 = warp * 4; i0 < pcnt; i0 += 64) {
                    int mcount = pcnt - i0; if (mcount > 4) mcount = 4;
                    int nid[4];
                    __syncwarp();
                    #pragma unroll
                    for (int m = 0; m < 4; m++) {
                        if (m < mcount) {
                            int n = g_tl_nodes[pbase + i0 + m];
                            nid[m] = n;
                            const float4* hsrc = (const float4*)(g_h + (size_t)n * Hv);
                            float4* dm = (float4*)(hbw + m * 256);
                            dm[lane] = hsrc[lane];
                            dm[lane + 32] = hsrc[lane + 32];
                        } else nid[m] = -1;
                    }
                    __syncwarp();
                    if (mcount == 1) {
                        unsigned long long af = 0;
                        #pragma unroll 8
                        for (int k4 = 0; k4 < 64; k4++) {
                            ulonglong2 wf = *(const ulonglong2*)&Wfh4[k4 * 128 + lane * 4];
                            ulonglong2 xv = *(const ulonglong2*)&hbw[k4 * 4];
                            FFMA2(af, xv.x, wf.x);
                            FFMA2(af, xv.y, wf.y);
                        }
                        g_fh[(size_t)nid[0] * Hv + J] = pairsum(af);
                    } else {
                        unsigned long long af[4] = {0,0,0,0};
                        #pragma unroll 4
                        for (int k4 = 0; k4 < 64; k4++) {
                            ulonglong2 wf = *(const ulonglong2*)&Wfh4[k4 * 128 + lane * 4];
                            #pragma unroll
                            for (int m = 0; m < 4; m++) {
                                ulonglong2 xv = *(const ulonglong2*)&hbw[m * 256 + k4 * 4];
                                FFMA2(af[m], xv.x, wf.x);
                                FFMA2(af[m], xv.y, wf.y);
                            }
                        }
                        #pragma unroll
                        for (int m = 0; m < 4; m++)
                            if (nid[m] >= 0)
                                g_fh[(size_t)nid[m] * Hv + J] = pairsum(af[m]);
                    }
                }
            }
            __syncthreads();   // fh (column-local) visible to CTA's gate-phase

            // (b) gate-phase: nodes of height lev
            {
                int base = g_tl_off[b * 32 + lev];
                int cnt  = g_tl_off[b * 32 + lev + 1] - base;
                for (int i0 = warp * 4; i0 < cnt; i0 += 64) {
                    int mcount = cnt - i0; if (mcount > 4) mcount = 4;
                    int nid[4]; float fcv[4];
                    __syncwarp();
                    #pragma unroll
                    for (int m = 0; m < 4; m++) {
                        fcv[m] = 0.0f;
                        if (m < mcount) {
                            int n = g_tl_nodes[base + i0 + m];
                            nid[m] = n;
                            float fxv = g_proj[1][(size_t)n * Hv + J];
                            int cs = g_coff[n], ce = g_coff[n + 1];
                            float4 s0 = make_float4(0,0,0,0), s1 = make_float4(0,0,0,0);
                            float fc = 0.0f;
                            for (int ci = cs; ci < ce; ci++) {
                                int ch = g_children[ci];
                                const float4* hsrc = (const float4*)(g_h + (size_t)ch * Hv);
                                float4 v0 = hsrc[lane], v1 = hsrc[lane + 32];
                                s0.x += v0.x; s0.y += v0.y; s0.z += v0.z; s0.w += v0.w;
                                s1.x += v1.x; s1.y += v1.y; s1.z += v1.z; s1.w += v1.w;
                                fc += sigf(g_fh[(size_t)ch * Hv + J] + fxv)
                                      * g_c[(size_t)ch * Hv + J];
                            }
                            float4* dm = (float4*)(hbw + m * 256);
                            dm[lane] = s0; dm[lane + 32] = s1;
                            fcv[m] = fc;
                        } else nid[m] = -1;
                    }
                    __syncwarp();
                    if (mcount == 1) {
                        unsigned long long ai = 0, ao = 0, au = 0;
                        #pragma unroll 4
                        for (int k4 = 0; k4 < 64; k4++) {
                            ulonglong2 xv = *(const ulonglong2*)&hbw[k4 * 4];
                            ulonglong2 wi = *(const ulonglong2*)&Wih4[k4 * 128 + lane * 4];
                            ulonglong2 wo = *(const ulonglong2*)&Woh4[k4 * 128 + lane * 4];
                            ulonglong2 wu = *(const ulonglong2*)&Wuh4[k4 * 128 + lane * 4];
                            FFMA2(ai, xv.x, wi.x); FFMA2(ai, xv.y, wi.y);
                            FFMA2(ao, xv.x, wo.x); FFMA2(ao, xv.y, wo.y);
                            FFMA2(au, xv.x, wu.x); FFMA2(au, xv.y, wu.y);
                        }
                        size_t nidx = (size_t)nid[0] * Hv + J;
                        float iv = sigf(g_proj[0][nidx] + pairsum(ai));
                        float ov = sigf(g_proj[2][nidx] + pairsum(ao));
                        float uv = __tanhf(g_proj[3][nidx] + pairsum(au));
                        float cn = iv * uv + fcv[0];
                        g_c[nidx] = cn;
                        g_h[nidx] = ov * __tanhf(cn);
                    } else {
                        unsigned long long ai[4] = {0,0,0,0};
                        unsigned long long ao[4] = {0,0,0,0};
                        unsigned long long au[4] = {0,0,0,0};
                        #pragma unroll 2
                        for (int k4 = 0; k4 < 64; k4++) {
                            ulonglong2 wi = *(const ulonglong2*)&Wih4[k4 * 128 + lane * 4];
                            ulonglong2 wo = *(const ulonglong2*)&Woh4[k4 * 128 + lane * 4];
                            ulonglong2 wu = *(const ulonglong2*)&Wuh4[k4 * 128 + lane * 4];
                            #pragma unroll
                            for (int m = 0; m < 4; m++) {
                                ulonglong2 xv = *(const ulonglong2*)&hbw[m * 256 + k4 * 4];
                                FFMA2(ai[m], xv.x, wi.x); FFMA2(ai[m], xv.y, wi.y);
                                FFMA2(ao[m], xv.x, wo.x); FFMA2(ao[m], xv.y, wo.y);
                                FFMA2(au[m], xv.x, wu.x); FFMA2(au[m], xv.y, wu.y);
                            }
                        }
                        #pragma unroll
                        for (int m = 0; m < 4; m++) {
                            if (nid[m] < 0) continue;
                            size_t nidx = (size_t)nid[m] * Hv + J;
                            float iv = sigf(g_proj[0][nidx] + pairsum(ai[m]));
                            float ov = sigf(g_proj[2][nidx] + pairsum(ao[m]));
                            float uv = __tanhf(g_proj[3][nidx] + pairsum(au[m]));
                            float cn = iv * uv + fcv[m];
                            g_c[nidx] = cn;
                            g_h[nidx] = ov * __tanhf(cn);
                        }
                    }
                }
            }
            tree_bar(b);
        }
    }

    // ---- P4: per-tree max-pool + output head ------------------------------
    {
        int col = g * 32 + lane;
        float m = -1e30f;
        for (int s = warp; s < Sv; s += 16)
            m = fmaxf(m, g_h[(size_t)(b * Sv + s) * Hv + col]);
        scratch[warp * 32 + lane] = m;
        __syncthreads();
        if (tid < 32) {
            float mm = scratch[tid];
            #pragma unroll
            for (int r = 1; r < 16; r++) mm = fmaxf(mm, scratch[r * 32 + tid]);
            g_pooled[b * Hv + g * 32 + tid] = mm;
        }
    }
    tree_bar(b);
    if (g == 0 && warp < Lv) {
        float acc = 0.0f;
        for (int k = lane; k < Hv; k += 32)
            acc += g_pooled[b * Hv + k] * W_out[k * Lv + warp];
        #pragma unroll
        for (int off = 16; off; off >>= 1)
            acc += __shfl_down_sync(0xFFFFFFFFu, acc, off);
        if (lane == 0) out[b * Lv + warp] = acc + b_out[warp];
    }
}

// ---------------- launch --------------------------------------------------
extern "C" void kernel_launch(void* const* d_in, const int* in_sizes, int n_in,
                              void* d_out, int out_size) {
    const int s = (n_in >= 22) ? 1 : 0;   // robust to n_levels scalar presence
    const int* xs          = (const int*)d_in[0];
    const int* rels        = (const int*)d_in[1];
    const int* child_idx   = (const int*)d_in[2];
    const int* parent_idx  = (const int*)d_in[3];
    const int* node_height = (const int*)d_in[4];
    const float* emb_W = (const float*)d_in[5 + s];
    const float* rel_W = (const float*)d_in[6 + s];
    const float* W_ix  = (const float*)d_in[7 + s];
    const float* b_ix  = (const float*)d_in[8 + s];
    const float* W_ih  = (const float*)d_in[9 + s];
    const float* b_ih  = (const float*)d_in[10 + s];
    const float* W_fx  = (const float*)d_in[11 + s];
    const float* b_fx  = (const float*)d_in[12 + s];
    const float* W_fh  = (const float*)d_in[13 + s];
    const float* b_fh  = (const float*)d_in[14 + s];
    const float* W_ox  = (const float*)d_in[15 + s];
    const float* W_oh  = (const float*)d_in[16 + s];
    const float* W_ux  = (const float*)d_in[17 + s];
    const float* W_uh  = (const float*)d_in[18 + s];
    const float* W_out = (const float*)d_in[19 + s];
    const float* b_out = (const float*)d_in[20 + s];
    float* out = (float*)d_out;

    cudaFuncSetAttribute(main_kernel, cudaFuncAttributeMaxDynamicSharedMemorySize, SMEM_BYTES);

    setup_kernel<<<1, 1024>>>(child_idx, parent_idx, node_height);
    main_kernel<<<NCTA, NTHR, SMEM_BYTES>>>(xs, rels, emb_W, rel_W,
                                            W_ix, b_ix, W_ih, b_ih,
                                            W_fx, b_fx, W_fh, b_fh,
                                            W_ox, W_oh, W_ux, W_uh,
                                            W_out, b_out, out);
}